// round 2
// baseline (speedup 1.0000x reference)
#include <cuda_runtime.h>

#define NN 50000
#define DD 128

// scratch (static __device__ — no allocation allowed)
__device__ __align__(16) float g_deg[NN];              // degree -> dinv in place
__device__ __align__(16) float g_y[(size_t)NN * DD];   // aggregated features y = A_hat @ x

// ---------------- degree / dinv ----------------
__global__ void k_deg_init(int n) {
    int i = blockIdx.x * blockDim.x + threadIdx.x;
    if (i < n) g_deg[i] = 1.0f;  // self loop
}

__global__ void k_deg_edges(const int* __restrict__ dst, int e_cnt) {
    int i = blockIdx.x * blockDim.x + threadIdx.x;
    if (i < e_cnt) {
        unsigned d = (unsigned)dst[i];
        if (d < NN) atomicAdd(&g_deg[d], 1.0f);
    }
}

__global__ void k_dinv(int n) {
    int i = blockIdx.x * blockDim.x + threadIdx.x;
    if (i < n) g_deg[i] = rsqrtf(g_deg[i]);
}

// ---------------- y init with self loop: y = x * dinv^2 ----------------
__global__ void k_y_init(const float* __restrict__ x, int n) {
    int i = blockIdx.x * blockDim.x + threadIdx.x;  // over n * 32 float4s
    if (i < n * 32) {
        int node = i >> 5;
        float di = g_deg[node];
        float s = di * di;
        float4 v = ((const float4*)x)[i];
        v.x *= s; v.y *= s; v.z *= s; v.w *= s;
        ((float4*)g_y)[i] = v;
    }
}

// ---------------- edge aggregation: y[dst] += x[src] * dinv[s]*dinv[d] ----------------
// one warp per edge, one float4 per lane, vector RED to cut atomic count 4x
__global__ void k_agg(const float* __restrict__ x,
                      const int* __restrict__ src,
                      const int* __restrict__ dst,
                      int e_cnt) {
    long long gid = (long long)blockIdx.x * blockDim.x + threadIdx.x;
    int e = (int)(gid >> 5);
    int lane = (int)(gid & 31);
    if (e >= e_cnt) return;
    unsigned s = (unsigned)__ldg(src + e);
    unsigned d = (unsigned)__ldg(dst + e);
    if (s >= NN || d >= NN) return;   // never trap on bad indices
    float norm = g_deg[s] * g_deg[d];
    float4 xv = __ldg(((const float4*)(x + (size_t)s * DD)) + lane);
    float* addr = g_y + (size_t)d * DD + lane * 4;
    asm volatile("red.global.add.v4.f32 [%0], {%1, %2, %3, %4};"
                 :: "l"(addr),
                    "f"(xv.x * norm), "f"(xv.y * norm),
                    "f"(xv.z * norm), "f"(xv.w * norm)
                 : "memory");
}

// ---------------- fused dual GEMM + bias + relu + mean ----------------
// out = 0.5 * (relu(y@W1 + b1) + relu(y@W2 + b2))
// BM=64 nodes per block, 256 threads, packed fp32x2 FMA (Blackwell)

__device__ __forceinline__ void ffma2(unsigned long long& d,
                                      unsigned long long a,
                                      unsigned long long b) {
    asm volatile("fma.rn.f32x2 %0, %1, %2, %0;" : "+l"(d) : "l"(a), "l"(b));
}

#define BM 64

extern "C" __global__ void __launch_bounds__(256, 1)
k_gemm_fused(const float* __restrict__ W1, const float* __restrict__ b1,
             const float* __restrict__ W2, const float* __restrict__ b2,
             float* __restrict__ out, int n) {
    extern __shared__ float smem[];
    float* W1s = smem;                 // 128*128
    float* W2s = smem + 16384;         // 128*128
    float* Ys  = smem + 32768;         // BM*128

    int tid = threadIdx.x;
    int m0 = blockIdx.x * BM;

    // load weights (16384 floats each) via float4
    for (int i = tid; i < 4096; i += 256) {
        ((float4*)W1s)[i] = ((const float4*)W1)[i];
        ((float4*)W2s)[i] = ((const float4*)W2)[i];
    }
    // load y tile
    for (int i = tid; i < BM * 32; i += 256) {
        int row = i >> 5;
        int g = m0 + row;
        float4 v;
        if (g < n) v = ((const float4*)g_y)[(size_t)g * 32 + (i & 31)];
        else       v = make_float4(0.f, 0.f, 0.f, 0.f);
        ((float4*)Ys)[i] = v;
    }
    __syncthreads();

    int cg = tid & 15;        // 16 col-groups of 8 cols
    int ng = tid >> 4;        // 16 node-groups of 4 nodes
    int col0 = cg * 8;
    int row0 = ng * 4;

    unsigned long long acc1[4][4];
    unsigned long long acc2[4][4];
    #pragma unroll
    for (int i = 0; i < 4; i++)
        #pragma unroll
        for (int j = 0; j < 4; j++) { acc1[i][j] = 0ull; acc2[i][j] = 0ull; }

    #pragma unroll 4
    for (int k = 0; k < 128; k++) {
        ulonglong2 w1a = *reinterpret_cast<const ulonglong2*>(&W1s[k * 128 + col0]);
        ulonglong2 w1b = *reinterpret_cast<const ulonglong2*>(&W1s[k * 128 + col0 + 4]);
        ulonglong2 w2a = *reinterpret_cast<const ulonglong2*>(&W2s[k * 128 + col0]);
        ulonglong2 w2b = *reinterpret_cast<const ulonglong2*>(&W2s[k * 128 + col0 + 4]);
        #pragma unroll
        for (int i = 0; i < 4; i++) {
            float yv = Ys[(row0 + i) * 128 + k];
            unsigned long long yy;
            asm("mov.b64 %0, {%1, %1};" : "=l"(yy) : "r"(__float_as_uint(yv)));
            ffma2(acc1[i][0], yy, w1a.x);
            ffma2(acc1[i][1], yy, w1a.y);
            ffma2(acc1[i][2], yy, w1b.x);
            ffma2(acc1[i][3], yy, w1b.y);
            ffma2(acc2[i][0], yy, w2a.x);
            ffma2(acc2[i][1], yy, w2a.y);
            ffma2(acc2[i][2], yy, w2b.x);
            ffma2(acc2[i][3], yy, w2b.y);
        }
    }

    // epilogue: bias + relu + mean
    #pragma unroll
    for (int i = 0; i < 4; i++) {
        int g = m0 + row0 + i;
        if (g >= n) continue;
        float* o = out + (size_t)g * 128 + col0;
        #pragma unroll
        for (int j = 0; j < 4; j++) {
            float a1x, a1y, a2x, a2y;
            asm("mov.b64 {%0, %1}, %2;" : "=f"(a1x), "=f"(a1y) : "l"(acc1[i][j]));
            asm("mov.b64 {%0, %1}, %2;" : "=f"(a2x), "=f"(a2y) : "l"(acc2[i][j]));
            int c = col0 + j * 2;
            float r1x = fmaxf(a1x + b1[c],     0.f);
            float r1y = fmaxf(a1y + b1[c + 1], 0.f);
            float r2x = fmaxf(a2x + b2[c],     0.f);
            float r2y = fmaxf(a2y + b2[c + 1], 0.f);
            o[j * 2]     = 0.5f * (r1x + r2x);
            o[j * 2 + 1] = 0.5f * (r1y + r2y);
        }
    }
}

extern "C" void kernel_launch(void* const* d_in, const int* in_sizes, int n_in,
                              void* d_out, int out_size) {
    const float* x  = (const float*)d_in[0];
    const int*   ei = (const int*)d_in[1];     // edge_index delivered as int32
    const float* W1 = (const float*)d_in[2];
    const float* b1 = (const float*)d_in[3];
    const float* W2 = (const float*)d_in[4];
    const float* b2 = (const float*)d_in[5];
    float* out = (float*)d_out;

    int n_nodes = in_sizes[0] / DD;       // 50000
    int n_edges = in_sizes[1] / 2;        // 600000
    const int* src = ei;
    const int* dst = ei + n_edges;

    // degree + dinv
    k_deg_init<<<(n_nodes + 255) / 256, 256>>>(n_nodes);
    k_deg_edges<<<(n_edges + 255) / 256, 256>>>(dst, n_edges);
    k_dinv<<<(n_nodes + 255) / 256, 256>>>(n_nodes);

    // y = dinv^2 * x (self loop) then scatter edges
    k_y_init<<<(n_nodes * 32 + 255) / 256, 256>>>(x, n_nodes);
    {
        long long threads = (long long)n_edges * 32;
        int blocks = (int)((threads + 255) / 256);
        k_agg<<<blocks, 256>>>(x, src, dst, n_edges);
    }

    // fused dual GEMM + epilogue
    int smem_bytes = (16384 * 2 + BM * 128) * 4;   // 163840
    cudaFuncSetAttribute(k_gemm_fused,
                         cudaFuncAttributeMaxDynamicSharedMemorySize, smem_bytes);
    int gblocks = (n_nodes + BM - 1) / BM;
    k_gemm_fused<<<gblocks, 256, smem_bytes>>>(W1, b1, W2, b2, out, n_nodes);
}

// round 3
// speedup vs baseline: 1.8100x; 1.8100x over previous
#include <cuda_runtime.h>

#define NN 50000
#define NE_MAX 700000
#define DD 128

// scratch (static __device__ — no allocation allowed)
__device__ int   g_cnt[NN];                            // in-degree histogram
__device__ int   g_off[NN + 1];                        // CSR offsets (exclusive scan)
__device__ int   g_cur[NN];                            // scatter cursors
__device__ int   g_bsums[64];                          // block sums for scan
__device__ float g_dinv[NN];                           // 1/sqrt(deg+1)
__device__ int   g_src_sorted[NE_MAX];                 // edge srcs sorted by dst
__device__ __align__(16) float g_y[(size_t)NN * DD];   // y = A_hat @ x

// ---------------- histogram ----------------
__global__ void k_zero(int n) {
    int i = blockIdx.x * blockDim.x + threadIdx.x;
    if (i < n) g_cnt[i] = 0;
}

__global__ void k_hist(const int* __restrict__ src, const int* __restrict__ dst, int e) {
    int i = blockIdx.x * blockDim.x + threadIdx.x;
    if (i < e) {
        unsigned s = (unsigned)src[i], d = (unsigned)dst[i];
        if (s < NN && d < NN) atomicAdd(&g_cnt[d], 1);
    }
}

// ---------------- exclusive scan (3 phases) ----------------
__global__ void k_scan1(int n) {
    __shared__ int sm[1024];
    int tid = threadIdx.x;
    int gid = blockIdx.x * 1024 + tid;
    int v = (gid < n) ? g_cnt[gid] : 0;
    sm[tid] = v;
    __syncthreads();
    for (int ofs = 1; ofs < 1024; ofs <<= 1) {
        int t = (tid >= ofs) ? sm[tid - ofs] : 0;
        __syncthreads();
        sm[tid] += t;
        __syncthreads();
    }
    if (gid < n) g_off[gid] = sm[tid] - v;   // block-local exclusive
    if (tid == 1023) g_bsums[blockIdx.x] = sm[1023];
}

__global__ void k_scan2(int nblocks) {
    if (threadIdx.x == 0 && blockIdx.x == 0) {
        int run = 0;
        for (int i = 0; i < nblocks; i++) {
            int v = g_bsums[i];
            g_bsums[i] = run;
            run += v;
        }
        g_off[NN] = run;   // total valid edges
    }
}

__global__ void k_scan3(int n) {
    int i = blockIdx.x * blockDim.x + threadIdx.x;
    if (i < n) {
        int o = g_off[i] + g_bsums[i >> 10];
        g_off[i] = o;
        g_cur[i] = o;
        g_dinv[i] = rsqrtf((float)g_cnt[i] + 1.0f);   // +1 self loop
    }
}

// ---------------- scatter edges into dst-sorted order ----------------
__global__ void k_scatter(const int* __restrict__ src, const int* __restrict__ dst, int e) {
    int i = blockIdx.x * blockDim.x + threadIdx.x;
    if (i < e) {
        unsigned s = (unsigned)src[i], d = (unsigned)dst[i];
        if (s < NN && d < NN) {
            int p = atomicAdd(&g_cur[d], 1);
            if (p < NE_MAX) g_src_sorted[p] = (int)s;
        }
    }
}

// ---------------- CSR gather-aggregate: y[d] = sum + self, no atomics ----------------
// one warp per dst node, one float4 per lane, unroll-4 over edges for MLP
__global__ void __launch_bounds__(256) k_agg_gather(const float* __restrict__ x, int n) {
    int warp = (blockIdx.x * blockDim.x + threadIdx.x) >> 5;
    int lane = threadIdx.x & 31;
    if (warp >= n) return;
    int d = warp;

    float dd = g_dinv[d];
    float4 acc = __ldg((const float4*)x + (size_t)d * 32 + lane);
    float ss = dd * dd;
    acc.x *= ss; acc.y *= ss; acc.z *= ss; acc.w *= ss;

    int beg = g_off[d], end = g_off[d + 1];
    int j = beg;
    for (; j + 4 <= end; j += 4) {
        int s0 = __ldg(g_src_sorted + j);
        int s1 = __ldg(g_src_sorted + j + 1);
        int s2 = __ldg(g_src_sorted + j + 2);
        int s3 = __ldg(g_src_sorted + j + 3);
        float n0 = g_dinv[s0] * dd;
        float n1 = g_dinv[s1] * dd;
        float n2 = g_dinv[s2] * dd;
        float n3 = g_dinv[s3] * dd;
        float4 v0 = __ldg((const float4*)x + (size_t)s0 * 32 + lane);
        float4 v1 = __ldg((const float4*)x + (size_t)s1 * 32 + lane);
        float4 v2 = __ldg((const float4*)x + (size_t)s2 * 32 + lane);
        float4 v3 = __ldg((const float4*)x + (size_t)s3 * 32 + lane);
        acc.x += v0.x * n0 + v1.x * n1 + v2.x * n2 + v3.x * n3;
        acc.y += v0.y * n0 + v1.y * n1 + v2.y * n2 + v3.y * n3;
        acc.z += v0.z * n0 + v1.z * n1 + v2.z * n2 + v3.z * n3;
        acc.w += v0.w * n0 + v1.w * n1 + v2.w * n2 + v3.w * n3;
    }
    for (; j < end; j++) {
        int s0 = __ldg(g_src_sorted + j);
        float n0 = g_dinv[s0] * dd;
        float4 v0 = __ldg((const float4*)x + (size_t)s0 * 32 + lane);
        acc.x += v0.x * n0; acc.y += v0.y * n0;
        acc.z += v0.z * n0; acc.w += v0.w * n0;
    }
    ((float4*)g_y)[(size_t)d * 32 + lane] = acc;
}

// ---------------- fused dual GEMM + bias + relu + mean ----------------
__device__ __forceinline__ void ffma2(unsigned long long& d,
                                      unsigned long long a,
                                      unsigned long long b) {
    asm volatile("fma.rn.f32x2 %0, %1, %2, %0;" : "+l"(d) : "l"(a), "l"(b));
}

#define BM 64

extern "C" __global__ void __launch_bounds__(256, 1)
k_gemm_fused(const float* __restrict__ W1, const float* __restrict__ b1,
             const float* __restrict__ W2, const float* __restrict__ b2,
             float* __restrict__ out, int n) {
    extern __shared__ float smem[];
    float* W1s = smem;                 // 128*128
    float* W2s = smem + 16384;         // 128*128
    float* Ys  = smem + 32768;         // BM*128

    int tid = threadIdx.x;
    int m0 = blockIdx.x * BM;

    for (int i = tid; i < 4096; i += 256) {
        ((float4*)W1s)[i] = ((const float4*)W1)[i];
        ((float4*)W2s)[i] = ((const float4*)W2)[i];
    }
    for (int i = tid; i < BM * 32; i += 256) {
        int row = i >> 5;
        int g = m0 + row;
        float4 v;
        if (g < n) v = ((const float4*)g_y)[(size_t)g * 32 + (i & 31)];
        else       v = make_float4(0.f, 0.f, 0.f, 0.f);
        ((float4*)Ys)[i] = v;
    }
    __syncthreads();

    int cg = tid & 15;
    int ng = tid >> 4;
    int col0 = cg * 8;
    int row0 = ng * 4;

    unsigned long long acc1[4][4];
    unsigned long long acc2[4][4];
    #pragma unroll
    for (int i = 0; i < 4; i++)
        #pragma unroll
        for (int j = 0; j < 4; j++) { acc1[i][j] = 0ull; acc2[i][j] = 0ull; }

    #pragma unroll 4
    for (int k = 0; k < 128; k++) {
        ulonglong2 w1a = *reinterpret_cast<const ulonglong2*>(&W1s[k * 128 + col0]);
        ulonglong2 w1b = *reinterpret_cast<const ulonglong2*>(&W1s[k * 128 + col0 + 4]);
        ulonglong2 w2a = *reinterpret_cast<const ulonglong2*>(&W2s[k * 128 + col0]);
        ulonglong2 w2b = *reinterpret_cast<const ulonglong2*>(&W2s[k * 128 + col0 + 4]);
        #pragma unroll
        for (int i = 0; i < 4; i++) {
            float yv = Ys[(row0 + i) * 128 + k];
            unsigned long long yy;
            asm("mov.b64 %0, {%1, %1};" : "=l"(yy) : "r"(__float_as_uint(yv)));
            ffma2(acc1[i][0], yy, w1a.x);
            ffma2(acc1[i][1], yy, w1a.y);
            ffma2(acc1[i][2], yy, w1b.x);
            ffma2(acc1[i][3], yy, w1b.y);
            ffma2(acc2[i][0], yy, w2a.x);
            ffma2(acc2[i][1], yy, w2a.y);
            ffma2(acc2[i][2], yy, w2b.x);
            ffma2(acc2[i][3], yy, w2b.y);
        }
    }

    #pragma unroll
    for (int i = 0; i < 4; i++) {
        int g = m0 + row0 + i;
        if (g >= n) continue;
        float* o = out + (size_t)g * 128 + col0;
        #pragma unroll
        for (int j = 0; j < 4; j++) {
            float a1x, a1y, a2x, a2y;
            asm("mov.b64 {%0, %1}, %2;" : "=f"(a1x), "=f"(a1y) : "l"(acc1[i][j]));
            asm("mov.b64 {%0, %1}, %2;" : "=f"(a2x), "=f"(a2y) : "l"(acc2[i][j]));
            int c = col0 + j * 2;
            float r1x = fmaxf(a1x + b1[c],     0.f);
            float r1y = fmaxf(a1y + b1[c + 1], 0.f);
            float r2x = fmaxf(a2x + b2[c],     0.f);
            float r2y = fmaxf(a2y + b2[c + 1], 0.f);
            o[j * 2]     = 0.5f * (r1x + r2x);
            o[j * 2 + 1] = 0.5f * (r1y + r2y);
        }
    }
}

extern "C" void kernel_launch(void* const* d_in, const int* in_sizes, int n_in,
                              void* d_out, int out_size) {
    const float* x  = (const float*)d_in[0];
    const int*   ei = (const int*)d_in[1];
    const float* W1 = (const float*)d_in[2];
    const float* b1 = (const float*)d_in[3];
    const float* W2 = (const float*)d_in[4];
    const float* b2 = (const float*)d_in[5];
    float* out = (float*)d_out;

    int n_nodes = in_sizes[0] / DD;       // 50000
    int n_edges = in_sizes[1] / 2;        // 600000
    const int* src = ei;
    const int* dst = ei + n_edges;

    int nb_nodes = (n_nodes + 255) / 256;
    int nb_edges = (n_edges + 255) / 256;
    int nscan = (n_nodes + 1023) / 1024;

    // CSR build: histogram -> scan -> scatter
    k_zero<<<nb_nodes, 256>>>(n_nodes);
    k_hist<<<nb_edges, 256>>>(src, dst, n_edges);
    k_scan1<<<nscan, 1024>>>(n_nodes);
    k_scan2<<<1, 32>>>(nscan);
    k_scan3<<<nb_nodes, 256>>>(n_nodes);
    k_scatter<<<nb_edges, 256>>>(src, dst, n_edges);

    // gather-aggregate (warp per node)
    {
        int warps = n_nodes;
        int blocks = (warps * 32 + 255) / 256;
        k_agg_gather<<<blocks, 256>>>(x, n_nodes);
    }

    // fused dual GEMM + epilogue
    int smem_bytes = (16384 * 2 + BM * 128) * 4;   // 163840
    cudaFuncSetAttribute(k_gemm_fused,
                         cudaFuncAttributeMaxDynamicSharedMemorySize, smem_bytes);
    int gblocks = (n_nodes + BM - 1) / BM;
    k_gemm_fused<<<gblocks, 256, smem_bytes>>>(W1, b1, W2, b2, out, n_nodes);
}